// round 15
// baseline (speedup 1.0000x reference)
#include <cuda_runtime.h>
#include <cstdint>

// ---------------------------------------------------------------------------
// ConvKanModel: feature planes precomputed to gmem by an elementwise kernel
// (silu + 11 cubic B-spline bases, norm+prelu folded for layer 2); the
// persistent FFMA2 conv then double-buffers channels via cp.async (pure async
// copy, no math, no register traffic) so staging fully overlaps compute.
// Compute inner loop = round-12 (best known) verbatim.
// ---------------------------------------------------------------------------

#define NB      4
#define CCH     16
#define KB      11
#define JF      12
#define HW      512
#define PLANE   (HW*HW)
#define TOTAL   (NB*CCH*PLANE)

#define TW      32
#define TH      16
#define HALOW   34
#define HALOH   18
#define HALO2   (HALOW*HALOH)     // 612
#define NW      (JF*3*3*CCH)      // 1728
#define ABUF    (JF*HALO2)        // 7344 words
#define NTILES  ((HW/TW)*(HW/TH)*NB)   // 2048
#define SMEM_WORDS (2*ABUF + 2*NW)     // 18144
#define SMEM_BYTES (SMEM_WORDS*4)      // 72576

#define GRID_P  444               // persistent CTAs (3 per SM)

__device__ float g_z1[TOTAL];
__device__ float g_z2[TOTAL];
__device__ float g_m1[64], g_r1[64], g_m2[64], g_r2[64];
__device__ unsigned int g_ctr[2];
__device__ float g_Wf[2*CCH*NW];                       // formatted weights
__device__ float g_feat[(size_t)NB*CCH*JF*PLANE];      // 805MB feature planes

typedef unsigned long long u64;

__device__ __forceinline__ u64 pack2(float x) {
    u64 r;
    asm("mov.b64 %0, {%1, %1};" : "=l"(r) : "f"(x));
    return r;
}
__device__ __forceinline__ void fma2(u64& d, u64 a, u64 b) {
    asm("fma.rn.f32x2 %0, %1, %2, %0;" : "+l"(d) : "l"(a), "l"(b));
}
__device__ __forceinline__ uint32_t smem_u32(const void* p) {
    uint32_t a;
    asm("{ .reg .u64 t; cvta.to.shared.u64 t, %1; cvt.u32.u64 %0, t; }"
        : "=r"(a) : "l"(p));
    return a;
}
__device__ __forceinline__ void cpa4(uint32_t dst, const float* src, uint32_t srcsz) {
    asm volatile("cp.async.ca.shared.global [%0], [%1], 4, %2;"
                 :: "r"(dst), "l"(src), "r"(srcsz) : "memory");
}
__device__ __forceinline__ void cpa16(uint32_t dst, const float* src) {
    asm volatile("cp.async.cg.shared.global [%0], [%1], 16;"
                 :: "r"(dst), "l"(src) : "memory");
}
#define CP_COMMIT() asm volatile("cp.async.commit_group;" ::: "memory")
#define CP_WAIT0()  asm volatile("cp.async.wait_group 0;" ::: "memory")

__global__ void reset_ctr() {
    if (threadIdx.x < 2) g_ctr[threadIdx.x] = 0u;
}

// ---- weight prep: layout [(j*9 + ky*3 + kx)*16 + o] per (layer, channel) ---
__global__ void prep_W(const float* __restrict__ bw1, const float* __restrict__ sw1,
                       const float* __restrict__ bw2, const float* __restrict__ sw2)
{
    const int l = blockIdx.x >> 4, c = blockIdx.x & 15;
    const float* bw = l ? bw2 : bw1;
    const float* sw = l ? sw2 : sw1;
    float* dst = g_Wf + (size_t)(l*CCH + c) * NW;
    for (int e = threadIdx.x; e < NW; e += blockDim.x) {
        const int o    = e & 15;
        const int rest = e >> 4;          // 0..107
        const int kx   = rest % 3;
        const int ky   = (rest / 3) % 3;
        const int j    = rest / 9;        // 0..11
        float v;
        if (j == 0) v = bw[((o*CCH + c)*3 + ky)*3 + kx];
        else        v = sw[((o*(CCH*KB) + c*KB + (j-1))*3 + ky)*3 + kx];
        dst[(j*9 + ky*3 + kx)*16 + o] = v;
    }
}

// ---- feature generation: 12 planes per (b,c), float4 vectorized ----------
template<bool NORM>
__global__ void featgen(const float* __restrict__ in,
                        const float* __restrict__ mean,
                        const float* __restrict__ rstd,
                        const float* __restrict__ alpha_p,
                        float* __restrict__ feat)
{
    const size_t i4 = (size_t)blockIdx.x * blockDim.x + threadIdx.x;
    if (i4 >= TOTAL/4) return;
    const int    bc = (int)(i4 >> 16);       // plane = 65536 float4
    const size_t q  = i4 & 65535;

    const float alpha = NORM ? alpha_p[0] : 0.0f;
    const float mu = NORM ? mean[bc] : 0.0f;
    const float rs = NORM ? rstd[bc] : 0.0f;

    const float4 x4 = reinterpret_cast<const float4*>(in)[i4];
    const float xs[4] = { x4.x, x4.y, x4.z, x4.w };
    float f[4][JF];
#pragma unroll
    for (int k = 0; k < 4; ++k) {
        float x = xs[k];
        if (NORM) {
            x = (x - mu) * rs;
            x = (x < 0.0f) ? alpha * x : x;            // prelu
        }
#pragma unroll
        for (int j = 0; j < JF; ++j) f[k][j] = 0.0f;
        f[k][0] = x / (1.0f + __expf(-x));             // silu
        const float u  = (x + 1.75f) * 4.0f;
        const float cf = floorf(u);
        const int   ci = (int)cf;
        if (ci >= 0 && ci < 14) {
            const float t = u - cf, mt = 1.0f - t, t2 = t*t, t3 = t2*t;
            const float w0 = mt*mt*mt * (1.0f/6.0f);
            const float w1 = (3.0f*t3 - 6.0f*t2 + 4.0f) * (1.0f/6.0f);
            const float w2 = (-3.0f*t3 + 3.0f*t2 + 3.0f*t + 1.0f) * (1.0f/6.0f);
            const float w3 = t3 * (1.0f/6.0f);
            if (ci >= 3)              f[k][ci-2] = w0;  // basis ci-3 -> slot j
            if (ci >= 2 && ci <= 12)  f[k][ci-1] = w1;
            if (ci >= 1 && ci <= 11)  f[k][ci  ] = w2;
            if (ci <= 10)             f[k][ci+1] = w3;
        }
    }
    float4* fp = reinterpret_cast<float4*>(feat + (size_t)bc * JF * PLANE) + q;
#pragma unroll
    for (int j = 0; j < JF; ++j) {
        float4 v;
        v.x = f[0][j]; v.y = f[1][j]; v.z = f[2][j]; v.w = f[3][j];
        fp[(size_t)j * (PLANE/4)] = v;
    }
}

// ---------------------------------------------------------------------------
// Persistent conv: 256 threads; steals 32x16 tiles; cp.async double buffer.
// tid: col = tid&31, rowgrp = (tid>>5)&3 (4 rows each), ohalf = tid>>7.
// ---------------------------------------------------------------------------
__global__ __launch_bounds__(256, 3)
void conv_cp(const float* __restrict__ feat,
             const float* __restrict__ gW,     // this layer's g_Wf slice
             float* __restrict__ out,
             int layer)
{
    extern __shared__ float smem[];
    const uint32_t sb = smem_u32(smem);
    __shared__ int s_tile;

    const int tid    = threadIdx.x;
    const int col    = tid & 31;
    const int rowgrp = (tid >> 5) & 3;
    const int ohalf  = tid >> 7;

    for (;;) {
        __syncthreads();   // protect s_tile + previous tile's smem reads
        if (tid == 0) s_tile = (int)atomicAdd(&g_ctr[layer], 1u);
        __syncthreads();
        const int t = s_tile;
        if (t >= NTILES) break;

        const int bx = (t & 15) * TW;
        const int by = ((t >> 4) & 31) * TH;
        const int b  = t >> 9;

        // halo addressing for this thread's 3 staging slots
        int h_off[3]; uint32_t h_sz[3]; int h_idx[3];
#pragma unroll
        for (int it = 0; it < 3; ++it) {
            const int idx = tid + it*256;
            const int iy = idx / HALOW;
            const int ix = idx - iy * HALOW;
            const int gy = by + iy - 1;
            const int gx = bx + ix - 1;
            const bool inb = (idx < HALO2) && gy >= 0 && gy < HW
                                           && gx >= 0 && gx < HW;
            h_idx[it] = idx;
            h_off[it] = inb ? (gy*HW + gx) : 0;
            h_sz[it]  = inb ? 4u : 0u;
        }

        u64 acc[4][4];
#pragma unroll
        for (int r = 0; r < 4; ++r)
#pragma unroll
            for (int p = 0; p < 4; ++p) acc[r][p] = 0ull;

        // ---- staging issuer (cp.async only, no math) ----
        auto issue = [&](int c, int p) {
            const float* fc = feat + ((size_t)(b*CCH + c) * JF) * PLANE;
            const uint32_t ab = sb + (uint32_t)(p*ABUF)*4u;
#pragma unroll
            for (int it = 0; it < 3; ++it) {
                if (h_idx[it] < HALO2) {
                    const float* src = fc + h_off[it];
                    const uint32_t d0 = ab + (uint32_t)h_idx[it]*4u;
#pragma unroll
                    for (int j = 0; j < JF; ++j)
                        cpa4(d0 + (uint32_t)(j*HALO2)*4u,
                             src + (size_t)j*PLANE, h_sz[it]);
                }
            }
            const float* wc = gW + (size_t)c * NW;
            const uint32_t wb = sb + (uint32_t)(2*ABUF + p*NW)*4u;
#pragma unroll
            for (int it = 0; it < 2; ++it) {
                const int e = tid + it*256;
                if (e < NW/4)
                    cpa16(wb + (uint32_t)e*16u, wc + e*4);
            }
        };

        // prologue: channel 0 into buffer 0
        issue(0, 0);
        CP_COMMIT();

        for (int c = 0; c < CCH; ++c) {
            CP_WAIT0();
            __syncthreads();   // group c visible to all; prev compute done
            if (c + 1 < CCH) { issue(c + 1, (c + 1) & 1); CP_COMMIT(); }

            // ---- compute channel c (round-12 inner loop) ----
            const float* s_act = smem + (c & 1)*ABUF;
            const float* s_w   = smem + 2*ABUF + (c & 1)*NW;
            const int rbase = rowgrp * 4;
#pragma unroll 1
            for (int j = 0; j < JF; ++j) {
                const float* actj = s_act + j*HALO2;
                const float* wj   = s_w + j*9*CCH + ohalf*8;
#pragma unroll
                for (int ky = 0; ky < 3; ++ky) {
                    u64 wv[3][4];
#pragma unroll
                    for (int kx = 0; kx < 3; ++kx) {
                        const ulonglong2* wp =
                            reinterpret_cast<const ulonglong2*>(wj + (ky*3 + kx)*CCH);
                        const ulonglong2 w01 = wp[0];
                        const ulonglong2 w23 = wp[1];
                        wv[kx][0] = w01.x; wv[kx][1] = w01.y;
                        wv[kx][2] = w23.x; wv[kx][3] = w23.y;
                    }
                    const float* arow = actj + (rbase + ky)*HALOW + col;
#pragma unroll
                    for (int kx = 0; kx < 3; ++kx) {
#pragma unroll
                        for (int r = 0; r < 4; ++r) {
                            const u64 a2 = pack2(arow[r*HALOW + kx]);
#pragma unroll
                            for (int p = 0; p < 4; ++p)
                                fma2(acc[r][p], a2, wv[kx][p]);
                        }
                    }
                }
            }
        }

        // ---- epilogue: unpack & write 4 pixels x 8 out channels ----
#pragma unroll
        for (int p = 0; p < 4; ++p) {
            const int o0 = ohalf*8 + 2*p;
            float* op0 = out + ((size_t)(b*CCH + o0    )) * PLANE;
            float* op1 = out + ((size_t)(b*CCH + o0 + 1)) * PLANE;
#pragma unroll
            for (int r = 0; r < 4; ++r) {
                const int gy = by + rowgrp*4 + r;
                const uint32_t lo = (uint32_t)(acc[r][p] & 0xffffffffull);
                const uint32_t hi = (uint32_t)(acc[r][p] >> 32);
                op0[gy*HW + bx + col] = __uint_as_float(lo);
                op1[gy*HW + bx + col] = __uint_as_float(hi);
            }
        }
    }
}

// ---------------------------------------------------------------------------
__global__ void stats_kernel(const float* __restrict__ z,
                             float* __restrict__ mean, float* __restrict__ rstd)
{
    __shared__ float sh_s[1024], sh_q[1024];
    const int bc = blockIdx.x;
    const float4* p = reinterpret_cast<const float4*>(z + (size_t)bc * PLANE);
    float s = 0.0f, q = 0.0f;
    for (int i = threadIdx.x; i < PLANE/4; i += 1024) {
        const float4 v = p[i];
        s += v.x + v.y + v.z + v.w;
        q += v.x*v.x + v.y*v.y + v.z*v.z + v.w*v.w;
    }
    sh_s[threadIdx.x] = s; sh_q[threadIdx.x] = q;
    __syncthreads();
    for (int off = 512; off > 0; off >>= 1) {
        if (threadIdx.x < off) {
            sh_s[threadIdx.x] += sh_s[threadIdx.x + off];
            sh_q[threadIdx.x] += sh_q[threadIdx.x + off];
        }
        __syncthreads();
    }
    if (threadIdx.x == 0) {
        const float m = sh_s[0] * (1.0f/PLANE);
        const float v = sh_q[0] * (1.0f/PLANE) - m*m;
        mean[bc] = m; rstd[bc] = rsqrtf(v + 1e-5f);
    }
}

__global__ void finalize_kernel(const float* __restrict__ z,
                                const float* __restrict__ mean,
                                const float* __restrict__ rstd,
                                const float* __restrict__ alpha_p,
                                float* __restrict__ out)
{
    const size_t i4 = (size_t)blockIdx.x * blockDim.x + threadIdx.x;
    if (i4 >= TOTAL/4) return;
    const int bc = (int)(i4 >> 16);
    const float alpha = alpha_p[0], m = mean[bc], rs = rstd[bc];
    float4 v = reinterpret_cast<const float4*>(z)[i4];
    float* vp = &v.x;
#pragma unroll
    for (int k = 0; k < 4; ++k) {
        float t = (vp[k] - m) * rs;
        t = (t < 0.0f) ? alpha * t : t;
        vp[k] = 1.0f / (1.0f + __expf(-t));
    }
    reinterpret_cast<float4*>(out)[i4] = v;
}

// ---------------------------------------------------------------------------
extern "C" void kernel_launch(void* const* d_in, const int* in_sizes, int n_in,
                              void* d_out, int out_size)
{
    const float* x   = (const float*)d_in[0];
    const float* bw1 = (const float*)d_in[1];
    const float* sw1 = (const float*)d_in[2];
    const float* a1  = (const float*)d_in[3];
    const float* bw2 = (const float*)d_in[4];
    const float* sw2 = (const float*)d_in[5];
    const float* a2  = (const float*)d_in[6];
    float* out = (float*)d_out;

    float *z1, *z2, *m1, *r1, *m2, *r2, *Wf, *feat;
    cudaGetSymbolAddress((void**)&z1, g_z1);
    cudaGetSymbolAddress((void**)&z2, g_z2);
    cudaGetSymbolAddress((void**)&m1, g_m1);
    cudaGetSymbolAddress((void**)&r1, g_r1);
    cudaGetSymbolAddress((void**)&m2, g_m2);
    cudaGetSymbolAddress((void**)&r2, g_r2);
    cudaGetSymbolAddress((void**)&Wf, g_Wf);
    cudaGetSymbolAddress((void**)&feat, g_feat);

    cudaFuncSetAttribute(conv_cp,
                         cudaFuncAttributeMaxDynamicSharedMemorySize, SMEM_BYTES);

    reset_ctr<<<1, 32>>>();
    prep_W<<<32, 256>>>(bw1, sw1, bw2, sw2);

    const int FG_BLOCKS = (TOTAL/4 + 255) / 256;   // 16384

    // Layer 1
    featgen<false><<<FG_BLOCKS, 256>>>(x, nullptr, nullptr, nullptr, feat);
    conv_cp<<<GRID_P, 256, SMEM_BYTES>>>(feat, Wf, z1, 0);
    stats_kernel<<<NB*CCH, 1024>>>(z1, m1, r1);

    // Layer 2 (norm+prelu folded into feature generation)
    featgen<true><<<FG_BLOCKS, 256>>>(z1, m1, r1, a1, feat);
    conv_cp<<<GRID_P, 256, SMEM_BYTES>>>(feat, Wf + (size_t)CCH*NW, z2, 1);
    stats_kernel<<<NB*CCH, 1024>>>(z2, m2, r2);

    finalize_kernel<<<(TOTAL/4 + 255)/256, 256>>>(z2, m2, r2, a2, out);
}